// round 9
// baseline (speedup 1.0000x reference)
#include <cuda_runtime.h>
#include <cuda_bf16.h>
#include <cstdint>
#include <cstddef>

// Problem constants
#define N_SRC0   286000
#define N_DST0   11000
#define N_E0     275000
#define N_DST1   1000
#define N_E1     10000
#define F_IN     602
#define HID      256
#define NCLS     41
#define KPAD     640          // 20 chunks of 32
#define F2       (F_IN / 2)   // 301
#define P2       (KPAD / 2)   // 320

// ---------------- scratch (device globals; no runtime allocation) ----------
__device__ int g_cnt0[N_DST0];
__device__ int g_cur0[N_DST0];
__device__ int g_off0[N_DST0 + 1];
__device__ int g_src0[N_E0];
__device__ int g_cnt1[N_DST1];
__device__ int g_cur1[N_DST1];
__device__ int g_off1[N_DST1 + 1];
__device__ int g_src1[N_E1];

// tf32-rounded fp32 operand buffers (padded to KPAD)
__device__ __align__(16) float g_xt  [(size_t)N_DST0 * KPAD];   // x[:11000] rna-rounded
__device__ __align__(16) float g_hagg[(size_t)N_DST0 * KPAD];   // layer-0 mean agg, rna-rounded
__device__ __align__(16) float g_wts [256 * KPAD];              // Wself0^T  [n][k]
__device__ __align__(16) float g_wtn [256 * KPAD];              // Wneigh0^T [n][k]

__device__ float g_h    [(size_t)N_DST0 * HID];
__device__ float g_hagg1[(size_t)N_DST1 * HID];

// round-to-nearest tf32 (unbiased)
__device__ __forceinline__ float tf32r(float v) {
    uint32_t o;
    asm("cvt.rna.tf32.f32 %0, %1;" : "=r"(o) : "f"(v));
    return __uint_as_float(o);
}

// ---------------- CSR build --------------------------------------------------
__global__ void k_zero() {
    int i = blockIdx.x * blockDim.x + threadIdx.x;
    if (i < N_DST0) { g_cnt0[i] = 0; g_cur0[i] = 0; }
    if (i < N_DST1) { g_cnt1[i] = 0; g_cur1[i] = 0; }
}

// fused: edge counting + weight transpose/round prep
#define CNT_BLKS  ((N_E0 + 255) / 256)           // 1075
#define PW_BLKS   ((2 * 256 * KPAD + 255) / 256) // 1280
__global__ void k_count_prepw(const int* __restrict__ e0_dst, const int* __restrict__ e1_dst,
                              const float* __restrict__ Ws, const float* __restrict__ Wn) {
    int bx = blockIdx.x;
    if (bx < CNT_BLKS) {
        int i = bx * 256 + threadIdx.x;
        if (i < N_E0) atomicAdd(&g_cnt0[e0_dst[i]], 1);
        if (i < N_E1) atomicAdd(&g_cnt1[e1_dst[i]], 1);
    } else {
        int idx = (bx - CNT_BLKS) * 256 + threadIdx.x;
        if (idx >= 2 * 256 * KPAD) return;
        int m = idx / (256 * KPAD);
        int r = idx % (256 * KPAD);
        int n = r / KPAD;
        int k = r % KPAD;
        const float* W = m ? Wn : Ws;
        float v = (k < F_IN) ? tf32r(W[(size_t)k * HID + n]) : 0.0f;
        if (m) g_wtn[n * KPAD + k] = v;
        else   g_wts[n * KPAD + k] = v;
    }
}

__device__ void scan_excl(const int* cnt, int* off, int n) {
    __shared__ int wsum[32];
    __shared__ int carry;
    const int t = threadIdx.x, lane = t & 31, w = t >> 5;
    if (t == 0) carry = 0;
    __syncthreads();
    for (int base = 0; base < n; base += 1024) {
        int i = base + t;
        int v = (i < n) ? cnt[i] : 0;
        int s = v;
        #pragma unroll
        for (int d = 1; d < 32; d <<= 1) { int u = __shfl_up_sync(~0u, s, d); if (lane >= d) s += u; }
        if (lane == 31) wsum[w] = s;
        __syncthreads();
        if (w == 0) {
            int ws = wsum[lane];
            #pragma unroll
            for (int d = 1; d < 32; d <<= 1) { int u = __shfl_up_sync(~0u, ws, d); if (lane >= d) ws += u; }
            wsum[lane] = ws;
        }
        __syncthreads();
        int woff = (w > 0) ? wsum[w - 1] : 0;
        if (i < n) off[i] = carry + woff + s - v;
        __syncthreads();
        if (t == 0) carry += wsum[31];
        __syncthreads();
    }
    if (threadIdx.x == 0) off[n] = carry;
}

__global__ void k_scan() {
    if (blockIdx.x == 0) scan_excl(g_cnt0, g_off0, N_DST0);
    else                 scan_excl(g_cnt1, g_off1, N_DST1);
}

// fused: edge scatter + x round/pad prep
#define PX_BLKS ((N_DST0 * P2 + 255) / 256)   // 13750
__global__ void k_scatter_prepx(const int* __restrict__ e0_src, const int* __restrict__ e0_dst,
                                const int* __restrict__ e1_src, const int* __restrict__ e1_dst,
                                const float* __restrict__ x) {
    int bx = blockIdx.x;
    if (bx < CNT_BLKS) {
        int i = bx * 256 + threadIdx.x;
        if (i < N_E0) {
            int d = e0_dst[i];
            int p = atomicAdd(&g_cur0[d], 1);
            g_src0[g_off0[d] + p] = e0_src[i];
        }
        if (i < N_E1) {
            int d = e1_dst[i];
            int p = atomicAdd(&g_cur1[d], 1);
            g_src1[g_off1[d] + p] = e1_src[i];
        }
    } else {
        int idx = (bx - CNT_BLKS) * 256 + threadIdx.x;
        if (idx >= N_DST0 * P2) return;
        int row = idx / P2;
        int p   = idx % P2;
        float2 v = make_float2(0.f, 0.f);
        if (p < F2) v = reinterpret_cast<const float2*>(x)[(size_t)row * F2 + p];
        float2 o; o.x = tf32r(v.x); o.y = tf32r(v.y);
        reinterpret_cast<float2*>(g_xt)[(size_t)row * P2 + p] = o;
    }
}

// ---------------- layer-0 mean aggregation (persistent, PDL primary) ---------
// 1184 blocks (8/SM), each strides over ~9 dsts. All blocks start in wave 1
// and release the dependent GEMM immediately via griddepcontrol.
#define AGG_BLKS 1184

__global__ __launch_bounds__(128) void k_agg0(const float* __restrict__ x) {
    asm volatile("griddepcontrol.launch_dependents;" ::: "memory");

    const int t = threadIdx.x;
    const bool has3 = (t + 256) < F2;

    for (int dst = blockIdx.x; dst < N_DST0; dst += AGG_BLKS) {
        const int beg = g_off0[dst];
        const int end = g_off0[dst + 1];

        float2 acc0 = make_float2(0.f, 0.f);
        float2 acc1 = make_float2(0.f, 0.f);
        float2 acc2 = make_float2(0.f, 0.f);

        int e = beg;
        for (; e + 4 <= end; e += 4) {
            const float2* r0 = reinterpret_cast<const float2*>(x + (size_t)g_src0[e + 0] * F_IN);
            const float2* r1 = reinterpret_cast<const float2*>(x + (size_t)g_src0[e + 1] * F_IN);
            const float2* r2 = reinterpret_cast<const float2*>(x + (size_t)g_src0[e + 2] * F_IN);
            const float2* r3 = reinterpret_cast<const float2*>(x + (size_t)g_src0[e + 3] * F_IN);
            float2 a0 = __ldg(r0 + t),       b0 = __ldg(r1 + t),       c0 = __ldg(r2 + t),       d0 = __ldg(r3 + t);
            float2 a1 = __ldg(r0 + t + 128), b1 = __ldg(r1 + t + 128), c1 = __ldg(r2 + t + 128), d1 = __ldg(r3 + t + 128);
            acc0.x += a0.x + b0.x + c0.x + d0.x;
            acc0.y += a0.y + b0.y + c0.y + d0.y;
            acc1.x += a1.x + b1.x + c1.x + d1.x;
            acc1.y += a1.y + b1.y + c1.y + d1.y;
            if (has3) {
                float2 a2 = __ldg(r0 + t + 256), b2 = __ldg(r1 + t + 256);
                float2 c2 = __ldg(r2 + t + 256), d2 = __ldg(r3 + t + 256);
                acc2.x += a2.x + b2.x + c2.x + d2.x;
                acc2.y += a2.y + b2.y + c2.y + d2.y;
            }
        }
        for (; e < end; ++e) {
            const float2* row = reinterpret_cast<const float2*>(x + (size_t)g_src0[e] * F_IN);
            float2 v0 = __ldg(row + t);
            float2 v1 = __ldg(row + t + 128);
            acc0.x += v0.x; acc0.y += v0.y;
            acc1.x += v1.x; acc1.y += v1.y;
            if (has3) {
                float2 v2 = __ldg(row + t + 256);
                acc2.x += v2.x; acc2.y += v2.y;
            }
        }

        const float inv = (end > beg) ? 1.0f / (float)(end - beg) : 0.0f;
        float2* o = reinterpret_cast<float2*>(g_hagg) + (size_t)dst * P2;
        float2 accs[3] = {acc0, acc1, acc2};
        #pragma unroll
        for (int j = 0; j < 3; ++j) {
            int p = t + j * 128;
            if (p >= P2) break;
            float2 ov;
            ov.x = (p < F2) ? tf32r(accs[j].x * inv) : 0.f;
            ov.y = (p < F2) ? tf32r(accs[j].y * inv) : 0.f;
            o[p] = ov;
        }
    }
}

// ---------------- tensor-core GEMM (TF32 mma.sync, PDL secondary) ------------
// Chunks 0-19 (x phase) run concurrently with k_agg0; griddepcontrol.wait
// before prefetching chunk 20 (agg phase).
#define BK        32
#define ROWPF     36                       // padded row length (floats)
#define A_T       (128 * ROWPF * 4)        // 18432 B
#define B_T       (64 * ROWPF * 4)         // 9216 B
#define BUF_SZ    (A_T + B_T)              // 27648 B
#define GEMM_SMEM (2 * BUF_SZ)             // 55296 B
#define NCH       40                       // 2 phases x 20 K-chunks

#define CP16(dst, src, pred) \
    asm volatile("cp.async.cg.shared.global [%0], [%1], 16, %2;" \
                 :: "r"(dst), "l"(src), "r"(pred))
#define CP_COMMIT() asm volatile("cp.async.commit_group;" ::: "memory")
#define CP_WAIT(n)  asm volatile("cp.async.wait_group %0;" :: "n"(n) : "memory")

__device__ __forceinline__ uint32_t smem_u32(const void* p) {
    uint32_t a;
    asm("{ .reg .u64 t; cvta.to.shared.u64 t, %1; cvt.u32.u64 %0, t; }" : "=r"(a) : "l"(p));
    return a;
}

__device__ __forceinline__ void mma_tf32(float* d,
                                         const uint32_t* a, const uint32_t* b) {
    asm volatile(
        "mma.sync.aligned.m16n8k8.row.col.f32.tf32.tf32.f32 "
        "{%0,%1,%2,%3}, {%4,%5,%6,%7}, {%8,%9}, {%0,%1,%2,%3};"
        : "+f"(d[0]), "+f"(d[1]), "+f"(d[2]), "+f"(d[3])
        : "r"(a[0]), "r"(a[1]), "r"(a[2]), "r"(a[3]), "r"(b[0]), "r"(b[1]));
}

__global__ __launch_bounds__(256, 3)
void k_gemm_mma(const float* __restrict__ bias) {
    extern __shared__ char smem[];
    const uint32_t sb = smem_u32(smem);
    const int tid  = threadIdx.x;
    const int lane = tid & 31;
    const int wid  = tid >> 5;
    const int warpM = wid & 3;            // 0..3
    const int warpN = wid >> 2;           // 0..1
    const int g  = lane >> 2;             // 0..7
    const int tg = lane & 3;              // 0..3
    const int rowBase = blockIdx.x * 128;
    const int colBase = blockIdx.y * 64;

    auto issue = [&](int c) {
        const int ph = (c >= 20);
        const int kb = (c - ph * 20) * BK;
        const float* A = ph ? g_hagg : g_xt;
        const float* B = ph ? g_wtn : g_wts;
        const uint32_t bufb = sb + (uint32_t)(c & 1) * BUF_SZ;

        #pragma unroll
        for (int u = 0; u < 4; ++u) {
            int idx = tid + u * 256;          // 0..1023
            int row = idx >> 3, v = idx & 7;
            int grow = rowBase + row;
            int pr = (grow < N_DST0) ? 16 : 0;
            size_t gb = ((size_t)grow * KPAD + kb + v * 4) * 4;
            if (grow >= N_DST0) gb = 0;
            uint32_t so = bufb + (uint32_t)(row * (ROWPF * 4) + v * 16);
            CP16(so, (const char*)A + gb, pr);
        }
        #pragma unroll
        for (int u = 0; u < 2; ++u) {
            int idx = tid + u * 256;          // 0..511
            int row = idx >> 3, v = idx & 7;
            size_t gb = ((size_t)(colBase + row) * KPAD + kb + v * 4) * 4;
            uint32_t so = bufb + (uint32_t)(A_T + row * (ROWPF * 4) + v * 16);
            CP16(so, (const char*)B + gb, 16);
        }
    };

    float acc[2][4][4] = {};   // [mtile][ntile][reg]

    issue(0);
    CP_COMMIT();

    for (int c = 0; c < NCH; ++c) {
        if (c + 1 < NCH) {
            if (c + 1 == 20)   // entering agg phase: wait for k_agg0 completion
                asm volatile("griddepcontrol.wait;" ::: "memory");
            issue(c + 1); CP_COMMIT(); CP_WAIT(1);
        } else {
            CP_WAIT(0);
        }
        __syncthreads();

        const char* buf = smem + (c & 1) * BUF_SZ;
        const char* As = buf;
        const char* Bs = buf + A_T;

        #pragma unroll
        for (int ks = 0; ks < 4; ++ks) {
            const int kbyte = (ks * 8 + tg) * 4;

            uint32_t a[2][4];
            #pragma unroll
            for (int mt = 0; mt < 2; ++mt) {
                int r0 = warpM * 32 + mt * 16 + g;
                a[mt][0] = *(const uint32_t*)(As + r0 * (ROWPF * 4) + kbyte);
                a[mt][1] = *(const uint32_t*)(As + (r0 + 8) * (ROWPF * 4) + kbyte);
                a[mt][2] = *(const uint32_t*)(As + r0 * (ROWPF * 4) + kbyte + 16);
                a[mt][3] = *(const uint32_t*)(As + (r0 + 8) * (ROWPF * 4) + kbyte + 16);
            }
            uint32_t b[4][2];
            #pragma unroll
            for (int nt = 0; nt < 4; ++nt) {
                int r = warpN * 32 + nt * 8 + g;
                b[nt][0] = *(const uint32_t*)(Bs + r * (ROWPF * 4) + kbyte);
                b[nt][1] = *(const uint32_t*)(Bs + r * (ROWPF * 4) + kbyte + 16);
            }
            #pragma unroll
            for (int mt = 0; mt < 2; ++mt)
                #pragma unroll
                for (int nt = 0; nt < 4; ++nt)
                    mma_tf32(acc[mt][nt], a[mt], b[nt]);
        }
        __syncthreads();
    }

    // ---- epilogue: bias + relu, float2 stores ----
    float2 bv[4];
    #pragma unroll
    for (int nt = 0; nt < 4; ++nt) {
        int col = colBase + warpN * 32 + nt * 8 + tg * 2;
        bv[nt].x = __ldg(bias + col);
        bv[nt].y = __ldg(bias + col + 1);
    }
    #pragma unroll
    for (int mt = 0; mt < 2; ++mt) {
        #pragma unroll
        for (int half = 0; half < 2; ++half) {
            int row = rowBase + warpM * 32 + mt * 16 + g + half * 8;
            if (row >= N_DST0) continue;
            #pragma unroll
            for (int nt = 0; nt < 4; ++nt) {
                int col = colBase + warpN * 32 + nt * 8 + tg * 2;
                float2 o;
                o.x = fmaxf(acc[mt][nt][half * 2 + 0] + bv[nt].x, 0.f);
                o.y = fmaxf(acc[mt][nt][half * 2 + 1] + bv[nt].y, 0.f);
                *(float2*)(g_h + (size_t)row * HID + col) = o;
            }
        }
    }
}

// ---------------- layer-1 mean aggregation -----------------------------------
__global__ void k_agg1() {
    const int dst = blockIdx.x;
    const int beg = g_off1[dst];
    const int end = g_off1[dst + 1];
    const int t   = threadIdx.x;

    float acc = 0.f;
    for (int e = beg; e < end; ++e)
        acc += g_h[(size_t)g_src1[e] * HID + t];

    const float inv = (end > beg) ? 1.0f / (float)(end - beg) : 0.0f;
    g_hagg1[(size_t)dst * HID + t] = acc * inv;
}

// ---------------- output layer -------------------------------------------------
__global__ void k_out(const float* __restrict__ Ws1,
                      const float* __restrict__ Wn1,
                      const float* __restrict__ b1,
                      float* __restrict__ out) {
    __shared__ float hd[HID];
    __shared__ float ha[HID];
    const int dst = blockIdx.x;
    for (int i = threadIdx.x; i < HID; i += blockDim.x) {
        hd[i] = g_h[(size_t)dst * HID + i];
        ha[i] = g_hagg1[(size_t)dst * HID + i];
    }
    __syncthreads();
    const int c = threadIdx.x;
    if (c < NCLS) {
        float s = b1[c];
        #pragma unroll 4
        for (int k = 0; k < HID; ++k)
            s += hd[k] * Ws1[k * NCLS + c] + ha[k] * Wn1[k * NCLS + c];
        out[dst * NCLS + c] = s;
    }
}

// ---------------- launch (single stream, graph-capture safe) -----------------
extern "C" void kernel_launch(void* const* d_in, const int* in_sizes, int n_in,
                              void* d_out, int out_size) {
    const float* x      = (const float*)d_in[0];
    const float* Wself0 = (const float*)d_in[1];
    const float* Wneigh0= (const float*)d_in[2];
    const float* b0     = (const float*)d_in[3];
    const float* Wself1 = (const float*)d_in[4];
    const float* Wneigh1= (const float*)d_in[5];
    const float* b1     = (const float*)d_in[6];
    const int*   e0_src = (const int*)d_in[7];
    const int*   e0_dst = (const int*)d_in[8];
    const int*   e1_src = (const int*)d_in[9];
    const int*   e1_dst = (const int*)d_in[10];
    float* out = (float*)d_out;

    static bool attr_set = false;
    if (!attr_set) {
        cudaFuncSetAttribute(k_gemm_mma, cudaFuncAttributeMaxDynamicSharedMemorySize, GEMM_SMEM);
        attr_set = true;
    }

    k_zero          <<<(N_DST0 + 255) / 256, 256>>>();
    k_count_prepw   <<<CNT_BLKS + PW_BLKS, 256>>>(e0_dst, e1_dst, Wself0, Wneigh0);
    k_scan          <<<2, 1024>>>();
    k_scatter_prepx <<<CNT_BLKS + PX_BLKS, 256>>>(e0_src, e0_dst, e1_src, e1_dst, x);
    k_agg0          <<<AGG_BLKS, 128>>>(x);

    // PDL: GEMM launches while agg0 runs; x-phase overlaps, agg-phase gated
    // by griddepcontrol.wait inside the kernel.
    {
        cudaLaunchConfig_t cfg = {};
        cfg.gridDim  = dim3((N_DST0 + 127) / 128, 4, 1);
        cfg.blockDim = dim3(256, 1, 1);
        cfg.dynamicSmemBytes = GEMM_SMEM;
        cfg.stream = 0;
        cudaLaunchAttribute attrs[1];
        attrs[0].id = cudaLaunchAttributeProgrammaticStreamSerialization;
        attrs[0].val.programmaticStreamSerializationAllowed = 1;
        cfg.attrs = attrs;
        cfg.numAttrs = 1;
        cudaLaunchKernelEx(&cfg, k_gemm_mma, b0);
    }

    k_agg1          <<<N_DST1, 256>>>();
    k_out           <<<N_DST1, 64>>>(Wself1, Wneigh1, b1, out);
}

// round 10
// speedup vs baseline: 1.1449x; 1.1449x over previous
#include <cuda_runtime.h>
#include <cuda_bf16.h>
#include <cstdint>
#include <cstddef>

// Problem constants
#define N_SRC0   286000
#define N_DST0   11000
#define N_E0     275000
#define N_DST1   1000
#define N_E1     10000
#define F_IN     602
#define HID      256
#define NCLS     41
#define KPAD     608          // 19 chunks of 32 (602 rounded up; no all-zero chunk)
#define F2       (F_IN / 2)   // 301
#define P2       (KPAD / 2)   // 304
#define KCH      19           // K-chunks per phase

// ---------------- scratch (device globals; no runtime allocation) ----------
__device__ int g_cnt0[N_DST0];
__device__ int g_cur0[N_DST0];
__device__ int g_off0[N_DST0 + 1];
__device__ int g_src0[N_E0];
__device__ int g_cnt1[N_DST1];
__device__ int g_cur1[N_DST1];
__device__ int g_off1[N_DST1 + 1];
__device__ int g_src1[N_E1];

// tf32-rounded fp32 operand buffers (padded to KPAD)
__device__ __align__(16) float g_xt  [(size_t)N_DST0 * KPAD];   // x[:11000] rna-rounded
__device__ __align__(16) float g_hagg[(size_t)N_DST0 * KPAD];   // layer-0 mean agg, rna-rounded
__device__ __align__(16) float g_wts [256 * KPAD];              // Wself0^T  [n][k]
__device__ __align__(16) float g_wtn [256 * KPAD];              // Wneigh0^T [n][k]

__device__ float g_h[(size_t)N_DST0 * HID];

// round-to-nearest tf32 (unbiased)
__device__ __forceinline__ float tf32r(float v) {
    uint32_t o;
    asm("cvt.rna.tf32.f32 %0, %1;" : "=r"(o) : "f"(v));
    return __uint_as_float(o);
}

// ---------------- CSR build --------------------------------------------------
__global__ void k_zero() {
    int i = blockIdx.x * blockDim.x + threadIdx.x;
    if (i < N_DST0) g_cnt0[i] = 0;
    if (i < N_DST1) g_cnt1[i] = 0;
}

// fused: edge counting + weight transpose/round prep
#define CNT_BLKS  ((N_E0 + 255) / 256)           // 1075
#define PW_BLKS   ((2 * 256 * KPAD + 255) / 256) // 1216
__global__ void k_count_prepw(const int* __restrict__ e0_dst, const int* __restrict__ e1_dst,
                              const float* __restrict__ Ws, const float* __restrict__ Wn) {
    int bx = blockIdx.x;
    if (bx < CNT_BLKS) {
        int i = bx * 256 + threadIdx.x;
        if (i < N_E0) atomicAdd(&g_cnt0[e0_dst[i]], 1);
        if (i < N_E1) atomicAdd(&g_cnt1[e1_dst[i]], 1);
    } else {
        int idx = (bx - CNT_BLKS) * 256 + threadIdx.x;
        if (idx >= 2 * 256 * KPAD) return;
        int m = idx / (256 * KPAD);
        int r = idx % (256 * KPAD);
        int n = r / KPAD;
        int k = r % KPAD;
        const float* W = m ? Wn : Ws;
        float v = (k < F_IN) ? tf32r(W[(size_t)k * HID + n]) : 0.0f;
        if (m) g_wtn[n * KPAD + k] = v;
        else   g_wts[n * KPAD + k] = v;
    }
}

// scan also zeroes g_cur (it already touches every dst index)
__device__ void scan_excl(const int* cnt, int* off, int* cur, int n) {
    __shared__ int wsum[32];
    __shared__ int carry;
    const int t = threadIdx.x, lane = t & 31, w = t >> 5;
    if (t == 0) carry = 0;
    __syncthreads();
    for (int base = 0; base < n; base += 1024) {
        int i = base + t;
        int v = (i < n) ? cnt[i] : 0;
        int s = v;
        #pragma unroll
        for (int d = 1; d < 32; d <<= 1) { int u = __shfl_up_sync(~0u, s, d); if (lane >= d) s += u; }
        if (lane == 31) wsum[w] = s;
        __syncthreads();
        if (w == 0) {
            int ws = wsum[lane];
            #pragma unroll
            for (int d = 1; d < 32; d <<= 1) { int u = __shfl_up_sync(~0u, ws, d); if (lane >= d) ws += u; }
            wsum[lane] = ws;
        }
        __syncthreads();
        int woff = (w > 0) ? wsum[w - 1] : 0;
        if (i < n) { off[i] = carry + woff + s - v; cur[i] = 0; }
        __syncthreads();
        if (t == 0) carry += wsum[31];
        __syncthreads();
    }
    if (threadIdx.x == 0) off[n] = carry;
}

__global__ void k_scan() {
    if (blockIdx.x == 0) scan_excl(g_cnt0, g_off0, g_cur0, N_DST0);
    else                 scan_excl(g_cnt1, g_off1, g_cur1, N_DST1);
}

// fused: edge scatter + x round/pad prep
#define PX_BLKS ((N_DST0 * P2 + 255) / 256)   // 13063
__global__ void k_scatter_prepx(const int* __restrict__ e0_src, const int* __restrict__ e0_dst,
                                const int* __restrict__ e1_src, const int* __restrict__ e1_dst,
                                const float* __restrict__ x) {
    int bx = blockIdx.x;
    if (bx < CNT_BLKS) {
        int i = bx * 256 + threadIdx.x;
        if (i < N_E0) {
            int d = e0_dst[i];
            int p = atomicAdd(&g_cur0[d], 1);
            g_src0[g_off0[d] + p] = e0_src[i];
        }
        if (i < N_E1) {
            int d = e1_dst[i];
            int p = atomicAdd(&g_cur1[d], 1);
            g_src1[g_off1[d] + p] = e1_src[i];
        }
    } else {
        int idx = (bx - CNT_BLKS) * 256 + threadIdx.x;
        if (idx >= N_DST0 * P2) return;
        int row = idx / P2;
        int p   = idx % P2;
        float2 v = make_float2(0.f, 0.f);
        if (p < F2) v = reinterpret_cast<const float2*>(x)[(size_t)row * F2 + p];
        float2 o; o.x = tf32r(v.x); o.y = tf32r(v.y);
        reinterpret_cast<float2*>(g_xt)[(size_t)row * P2 + p] = o;
    }
}

// ---------------- layer-0 mean aggregation (big gather) ----------------------
// 128 threads/block, 4-edge unroll: 12 independent LDG.64 in flight per thread.
__global__ void k_agg0(const float* __restrict__ x) {
    const int dst = blockIdx.x;
    const int beg = g_off0[dst];
    const int end = g_off0[dst + 1];
    const int t   = threadIdx.x;

    float2 acc0 = make_float2(0.f, 0.f);
    float2 acc1 = make_float2(0.f, 0.f);
    float2 acc2 = make_float2(0.f, 0.f);
    const bool has3 = (t + 256) < F2;

    int e = beg;
    for (; e + 4 <= end; e += 4) {
        const float2* r0 = reinterpret_cast<const float2*>(x + (size_t)g_src0[e + 0] * F_IN);
        const float2* r1 = reinterpret_cast<const float2*>(x + (size_t)g_src0[e + 1] * F_IN);
        const float2* r2 = reinterpret_cast<const float2*>(x + (size_t)g_src0[e + 2] * F_IN);
        const float2* r3 = reinterpret_cast<const float2*>(x + (size_t)g_src0[e + 3] * F_IN);
        float2 a0 = __ldg(r0 + t),       b0 = __ldg(r1 + t),       c0 = __ldg(r2 + t),       d0 = __ldg(r3 + t);
        float2 a1 = __ldg(r0 + t + 128), b1 = __ldg(r1 + t + 128), c1 = __ldg(r2 + t + 128), d1 = __ldg(r3 + t + 128);
        acc0.x += a0.x + b0.x + c0.x + d0.x;
        acc0.y += a0.y + b0.y + c0.y + d0.y;
        acc1.x += a1.x + b1.x + c1.x + d1.x;
        acc1.y += a1.y + b1.y + c1.y + d1.y;
        if (has3) {
            float2 a2 = __ldg(r0 + t + 256), b2 = __ldg(r1 + t + 256);
            float2 c2 = __ldg(r2 + t + 256), d2 = __ldg(r3 + t + 256);
            acc2.x += a2.x + b2.x + c2.x + d2.x;
            acc2.y += a2.y + b2.y + c2.y + d2.y;
        }
    }
    for (; e < end; ++e) {
        const float2* row = reinterpret_cast<const float2*>(x + (size_t)g_src0[e] * F_IN);
        float2 v0 = __ldg(row + t);
        float2 v1 = __ldg(row + t + 128);
        acc0.x += v0.x; acc0.y += v0.y;
        acc1.x += v1.x; acc1.y += v1.y;
        if (has3) {
            float2 v2 = __ldg(row + t + 256);
            acc2.x += v2.x; acc2.y += v2.y;
        }
    }

    const float inv = (end > beg) ? 1.0f / (float)(end - beg) : 0.0f;
    float2* o = reinterpret_cast<float2*>(g_hagg) + (size_t)dst * P2;
    float2 accs[3] = {acc0, acc1, acc2};
    #pragma unroll
    for (int j = 0; j < 3; ++j) {
        int p = t + j * 128;
        if (p >= P2) break;
        float2 ov;
        ov.x = (p < F2) ? tf32r(accs[j].x * inv) : 0.f;
        ov.y = (p < F2) ? tf32r(accs[j].y * inv) : 0.f;
        o[p] = ov;
    }
}

// ---------------- tensor-core GEMM via mma.sync (TF32, sm_80+ PTX) ----------
// h = relu([Xd | Hagg] @ [Ws; Wn] + b0), single-pass tf32 (inputs rna-rounded).
// CTA tile 128x64; grid (86, 4); 8 warps = 4(M) x 2(N); warp tile 32x32.
// Flattened 38-chunk double-buffered cp.async pipeline spanning both phases.
#define BK        32
#define ROWPF     36                       // padded row length (floats)
#define A_T       (128 * ROWPF * 4)        // 18432 B
#define B_T       (64 * ROWPF * 4)         // 9216 B
#define BUF_SZ    (A_T + B_T)              // 27648 B
#define GEMM_SMEM (2 * BUF_SZ)             // 55296 B
#define NCH       (2 * KCH)                // 38

#define CP16(dst, src, pred) \
    asm volatile("cp.async.cg.shared.global [%0], [%1], 16, %2;" \
                 :: "r"(dst), "l"(src), "r"(pred))
#define CP_COMMIT() asm volatile("cp.async.commit_group;" ::: "memory")
#define CP_WAIT(n)  asm volatile("cp.async.wait_group %0;" :: "n"(n) : "memory")

__device__ __forceinline__ uint32_t smem_u32(const void* p) {
    uint32_t a;
    asm("{ .reg .u64 t; cvta.to.shared.u64 t, %1; cvt.u32.u64 %0, t; }" : "=r"(a) : "l"(p));
    return a;
}

__device__ __forceinline__ void mma_tf32(float* d,
                                         const uint32_t* a, const uint32_t* b) {
    asm volatile(
        "mma.sync.aligned.m16n8k8.row.col.f32.tf32.tf32.f32 "
        "{%0,%1,%2,%3}, {%4,%5,%6,%7}, {%8,%9}, {%0,%1,%2,%3};"
        : "+f"(d[0]), "+f"(d[1]), "+f"(d[2]), "+f"(d[3])
        : "r"(a[0]), "r"(a[1]), "r"(a[2]), "r"(a[3]), "r"(b[0]), "r"(b[1]));
}

__global__ __launch_bounds__(256, 3)
void k_gemm_mma(const float* __restrict__ bias) {
    extern __shared__ char smem[];
    const uint32_t sb = smem_u32(smem);
    const int tid  = threadIdx.x;
    const int lane = tid & 31;
    const int wid  = tid >> 5;
    const int warpM = wid & 3;            // 0..3
    const int warpN = wid >> 2;           // 0..1
    const int g  = lane >> 2;             // 0..7
    const int tg = lane & 3;              // 0..3
    const int rowBase = blockIdx.x * 128;
    const int colBase = blockIdx.y * 64;

    auto issue = [&](int c) {
        const int ph = (c >= KCH);
        const int kb = (c - ph * KCH) * BK;
        const float* A = ph ? g_hagg : g_xt;
        const float* B = ph ? g_wtn : g_wts;
        const uint32_t bufb = sb + (uint32_t)(c & 1) * BUF_SZ;

        #pragma unroll
        for (int u = 0; u < 4; ++u) {
            int idx = tid + u * 256;          // 0..1023
            int row = idx >> 3, v = idx & 7;
            int grow = rowBase + row;
            int pr = (grow < N_DST0) ? 16 : 0;
            size_t gb = ((size_t)grow * KPAD + kb + v * 4) * 4;
            if (grow >= N_DST0) gb = 0;
            uint32_t so = bufb + (uint32_t)(row * (ROWPF * 4) + v * 16);
            CP16(so, (const char*)A + gb, pr);
        }
        #pragma unroll
        for (int u = 0; u < 2; ++u) {
            int idx = tid + u * 256;          // 0..511
            int row = idx >> 3, v = idx & 7;
            size_t gb = ((size_t)(colBase + row) * KPAD + kb + v * 4) * 4;
            uint32_t so = bufb + (uint32_t)(A_T + row * (ROWPF * 4) + v * 16);
            CP16(so, (const char*)B + gb, 16);
        }
    };

    float acc[2][4][4] = {};   // [mtile][ntile][reg]

    issue(0);
    CP_COMMIT();

    for (int c = 0; c < NCH; ++c) {
        if (c + 1 < NCH) { issue(c + 1); CP_COMMIT(); CP_WAIT(1); }
        else             { CP_WAIT(0); }
        __syncthreads();

        const char* buf = smem + (c & 1) * BUF_SZ;
        const char* As = buf;
        const char* Bs = buf + A_T;

        #pragma unroll
        for (int ks = 0; ks < 4; ++ks) {
            const int kbyte = (ks * 8 + tg) * 4;

            uint32_t a[2][4];
            #pragma unroll
            for (int mt = 0; mt < 2; ++mt) {
                int r0 = warpM * 32 + mt * 16 + g;
                a[mt][0] = *(const uint32_t*)(As + r0 * (ROWPF * 4) + kbyte);
                a[mt][1] = *(const uint32_t*)(As + (r0 + 8) * (ROWPF * 4) + kbyte);
                a[mt][2] = *(const uint32_t*)(As + r0 * (ROWPF * 4) + kbyte + 16);
                a[mt][3] = *(const uint32_t*)(As + (r0 + 8) * (ROWPF * 4) + kbyte + 16);
            }
            uint32_t b[4][2];
            #pragma unroll
            for (int nt = 0; nt < 4; ++nt) {
                int r = warpN * 32 + nt * 8 + g;
                b[nt][0] = *(const uint32_t*)(Bs + r * (ROWPF * 4) + kbyte);
                b[nt][1] = *(const uint32_t*)(Bs + r * (ROWPF * 4) + kbyte + 16);
            }
            #pragma unroll
            for (int mt = 0; mt < 2; ++mt)
                #pragma unroll
                for (int nt = 0; nt < 4; ++nt)
                    mma_tf32(acc[mt][nt], a[mt], b[nt]);
        }
        __syncthreads();
    }

    // ---- epilogue: bias + relu, float2 stores ----
    float2 bv[4];
    #pragma unroll
    for (int nt = 0; nt < 4; ++nt) {
        int col = colBase + warpN * 32 + nt * 8 + tg * 2;
        bv[nt].x = __ldg(bias + col);
        bv[nt].y = __ldg(bias + col + 1);
    }
    #pragma unroll
    for (int mt = 0; mt < 2; ++mt) {
        #pragma unroll
        for (int half = 0; half < 2; ++half) {
            int row = rowBase + warpM * 32 + mt * 16 + g + half * 8;
            if (row >= N_DST0) continue;
            #pragma unroll
            for (int nt = 0; nt < 4; ++nt) {
                int col = colBase + warpN * 32 + nt * 8 + tg * 2;
                float2 o;
                o.x = fmaxf(acc[mt][nt][half * 2 + 0] + bv[nt].x, 0.f);
                o.y = fmaxf(acc[mt][nt][half * 2 + 1] + bv[nt].y, 0.f);
                *(float2*)(g_h + (size_t)row * HID + col) = o;
            }
        }
    }
}

// ---------------- fused layer-1 aggregation + output layer -------------------
__global__ __launch_bounds__(256)
void k_agg1_out(const float* __restrict__ Ws1,
                const float* __restrict__ Wn1,
                const float* __restrict__ b1,
                float* __restrict__ out) {
    __shared__ float hd[HID];
    __shared__ float ha[HID];
    const int dst = blockIdx.x;
    const int t   = threadIdx.x;

    // mean aggregation for feature t (coalesced across the block per edge)
    const int beg = g_off1[dst];
    const int end = g_off1[dst + 1];
    float acc = 0.f;
    for (int e = beg; e < end; ++e)
        acc += g_h[(size_t)g_src1[e] * HID + t];
    const float inv = (end > beg) ? 1.0f / (float)(end - beg) : 0.0f;
    ha[t] = acc * inv;
    hd[t] = g_h[(size_t)dst * HID + t];     // h_dst1 = h[:1000]
    __syncthreads();

    if (t < NCLS) {
        float s = b1[t];
        #pragma unroll 4
        for (int k = 0; k < HID; ++k)
            s += hd[k] * Ws1[k * NCLS + t] + ha[k] * Wn1[k * NCLS + t];
        out[dst * NCLS + t] = s;
    }
}

// ---------------- launch (single stream, graph-capture safe) -----------------
extern "C" void kernel_launch(void* const* d_in, const int* in_sizes, int n_in,
                              void* d_out, int out_size) {
    const float* x      = (const float*)d_in[0];
    const float* Wself0 = (const float*)d_in[1];
    const float* Wneigh0= (const float*)d_in[2];
    const float* b0     = (const float*)d_in[3];
    const float* Wself1 = (const float*)d_in[4];
    const float* Wneigh1= (const float*)d_in[5];
    const float* b1     = (const float*)d_in[6];
    const int*   e0_src = (const int*)d_in[7];
    const int*   e0_dst = (const int*)d_in[8];
    const int*   e1_src = (const int*)d_in[9];
    const int*   e1_dst = (const int*)d_in[10];
    float* out = (float*)d_out;

    static bool attr_set = false;
    if (!attr_set) {
        cudaFuncSetAttribute(k_gemm_mma, cudaFuncAttributeMaxDynamicSharedMemorySize, GEMM_SMEM);
        attr_set = true;
    }

    k_zero          <<<(N_DST0 + 255) / 256, 256>>>();
    k_count_prepw   <<<CNT_BLKS + PW_BLKS, 256>>>(e0_dst, e1_dst, Wself0, Wneigh0);
    k_scan          <<<2, 1024>>>();
    k_scatter_prepx <<<CNT_BLKS + PX_BLKS, 256>>>(e0_src, e0_dst, e1_src, e1_dst, x);
    k_agg0          <<<N_DST0, 128>>>(x);
    k_gemm_mma      <<<dim3((N_DST0 + 127) / 128, 4), 256, GEMM_SMEM>>>(b0);
    k_agg1_out      <<<N_DST1, 256>>>(Wself1, Wneigh1, b1, out);
}